// round 13
// baseline (speedup 1.0000x reference)
#include <cuda_runtime.h>
#include <cuda_fp16.h>
#include <math.h>

#define H 64
#define NB 8
#define NL 2
#define MAXN 50000
#define MAXE 800000

// ---------------- scratch (device globals; no allocation allowed) ------------
__device__ __align__(256) float  g_x[MAXN * H];
__device__ __align__(256) __half g_Ph[MAXN * H];    // x@W1a + b1 (fp16)
__device__ __align__(256) __half g_Qh[MAXN * H];    // x@W1b      (fp16)
__device__ __align__(256) __half g_aggHh[MAXN * H]; // fp16 accumulator
__device__ __align__(256) __half g_eah[MAXE * NB];  // edge attrs (fp16)
__device__ __align__(256) int2   g_eidx[MAXE];      // packed (row, col)
__device__ __align__(256) float  g_deg[MAXN];

__device__ __forceinline__ float silu(float v) {
    return __fdividef(v, 1.0f + __expf(-v));
}

__device__ __forceinline__ unsigned h2_to_u(__half2 h) {
    return *reinterpret_cast<unsigned*>(&h);
}
__device__ __forceinline__ float2 u_to_f2(unsigned u) {
    __half2 h = *reinterpret_cast<__half2*>(&u);
    return __half22float2(h);
}

// ---------------- zero deg + out ----------------------------------------------
__global__ void k_zero2(float* __restrict__ a, int na, float* __restrict__ b, int nb) {
    int i = blockIdx.x * blockDim.x + threadIdx.x;
    int stride = gridDim.x * blockDim.x;
    for (; i < na; i += stride) a[i] = 0.0f;
    for (i = blockIdx.x * blockDim.x + threadIdx.x; i < nb; i += stride) b[i] = 0.0f;
}

// ---------------- edge_attr (fp16) + degree + packed index ---------------------
__global__ void k_edge_attr(const int* __restrict__ ei, const float* __restrict__ pos, int E) {
    int e = blockIdx.x * blockDim.x + threadIdx.x;
    int stride = gridDim.x * blockDim.x;
    const float PI = 3.14159265358979323846f;
    uint4* ea4 = (uint4*)g_eah;
    for (; e < E; e += stride) {
        int r = __ldg(&ei[e]), c = __ldg(&ei[E + e]);
        g_eidx[e] = make_int2(r, c);
        float dx = pos[r * 3 + 0] - pos[c * 3 + 0];
        float dy = pos[r * 3 + 1] - pos[c * 3 + 1];
        float dz = pos[r * 3 + 2] - pos[c * 3 + 2];
        float d = sqrtf(dx * dx + dy * dy + dz * dz);
        float env = 0.0f;
        if (d < 5.0f) {
            float cv = __cosf(d * (PI / 10.0f));
            env = cv * cv;
        }
        float inv = __fdividef(env, (d > 0.0f) ? d : 1.0f);
        float s1, c1;
        __sincosf(d * (PI / 5.0f), &s1, &c1);
        float twoc = 2.0f * c1;
        float sp = 0.0f, sc = s1;   // sin(k*theta) recurrence
        float v[NB];
#pragma unroll
        for (int j = 0; j < NB; j++) {
            v[j] = sc * inv;
            float sn = twoc * sc - sp;
            sp = sc; sc = sn;
        }
        uint4 u;
        u.x = h2_to_u(__floats2half2_rn(v[0], v[1]));
        u.y = h2_to_u(__floats2half2_rn(v[2], v[3]));
        u.z = h2_to_u(__floats2half2_rn(v[4], v[5]));
        u.w = h2_to_u(__floats2half2_rn(v[6], v[7]));
        ea4[e] = u;
        atomicAdd(&g_deg[c], 1.0f);
    }
}

// ---------------- P = x@W1a + b1, Q = x@W1b (fp16 out); zero aggH; opt gather ---
// lane l<16: P cols 4l..4l+3 ; lane>=16: Q cols 4(l-16)..
__global__ void k_pq(const float* __restrict__ w1, const float* __restrict__ b1,
                     const int* __restrict__ z, const float* __restrict__ embed, int N) {
    __shared__ float4 sB[64 * 32];   // [k][lane]
    __shared__ float4 sb1[16];
    __shared__ float4 sA4[8][64];    // 4 rows x 16 f4 per warp

    const float4* w1v = (const float4*)w1;
    for (int u = threadIdx.x; u < 64 * 32; u += blockDim.x) {
        int k = u >> 5, l = u & 31;
        sB[u] = (l < 16) ? w1v[k * 16 + l] : w1v[(64 + k) * 16 + (l - 16)];
    }
    if (threadIdx.x < 16) sb1[threadIdx.x] = ((const float4*)b1)[threadIdx.x];
    __syncthreads();

    int warp = threadIdx.x >> 5, lane = threadIdx.x & 31;
    int gw = (blockIdx.x * blockDim.x + threadIdx.x) >> 5;
    int nw = (gridDim.x * blockDim.x) >> 5;

    uint2* P2 = (uint2*)g_Ph;    // per node: 16 uint2 (4 halves each)
    uint2* Q2 = (uint2*)g_Qh;
    uint2* Z2 = (uint2*)g_aggHh; // per node: 16 uint2 (fp16 zero fill)
    float4* X4 = (float4*)g_x;
    const float4* E4 = (const float4*)embed;
    float* sA = (float*)sA4[warp];

    bool gather = (z != nullptr);

    for (int r0 = gw * 4; r0 < N; r0 += nw * 4) {
        int nr = min(4, N - r0);
        if (gather) {
            for (int t = lane; t < nr * 16; t += 32) {
                int rr = t >> 4, cc = t & 15;
                float4 v = E4[(size_t)__ldg(&z[r0 + rr]) * 16 + cc];
                sA4[warp][t] = v;
                X4[(size_t)(r0 + rr) * 16 + cc] = v;
            }
        } else {
            for (int t = lane; t < nr * 16; t += 32)
                sA4[warp][t] = X4[(size_t)r0 * 16 + t];
        }
        __syncwarp();

        float4 acc[4];
#pragma unroll
        for (int rr = 0; rr < 4; rr++)
            acc[rr] = (lane < 16) ? sb1[lane & 15] : make_float4(0.f, 0.f, 0.f, 0.f);

#pragma unroll 8
        for (int k = 0; k < 64; k++) {
            float4 b = sB[k * 32 + lane];
#pragma unroll
            for (int rr = 0; rr < 4; rr++) {
                float a = sA[rr * 64 + k];
                acc[rr].x = fmaf(a, b.x, acc[rr].x);
                acc[rr].y = fmaf(a, b.y, acc[rr].y);
                acc[rr].z = fmaf(a, b.z, acc[rr].z);
                acc[rr].w = fmaf(a, b.w, acc[rr].w);
            }
        }
        for (int rr = 0; rr < nr; rr++) {
            size_t b = (size_t)(r0 + rr) * 16;
            uint2 u;
            u.x = h2_to_u(__floats2half2_rn(acc[rr].x, acc[rr].y));
            u.y = h2_to_u(__floats2half2_rn(acc[rr].z, acc[rr].w));
            if (lane < 16) {
                P2[b + lane] = u;
                Z2[b + lane] = make_uint2(0u, 0u);
            } else {
                Q2[b + (lane - 16)] = u;
            }
        }
        __syncwarp();
    }
}

// ---------------- edge phase: aggH[c] += silu(P[c]+Q[r]+ea@W1c) ----------------
// QUARTER-warp (8 lanes) per edge; lane covers 8 output halves (uint4 gathers,
// red.v4.f16x2 flush) -> RED/gather lane-ops per edge halved vs 16-lane scheme
__global__ void __launch_bounds__(256, 6)
k_edge(const float* __restrict__ w1, int E) {
    __shared__ float4 sWc[NB * 16];   // 8 rows x 64 cols
    const float4* wc = (const float4*)(w1 + 128 * 64);
    for (int u = threadIdx.x; u < NB * 16; u += blockDim.x) sWc[u] = wc[u];
    __syncthreads();

    int lane = threadIdx.x & 31;
    int quad = lane >> 3;     // 0..3 : edge within warp-iteration
    int ql = lane & 7;        // 0..7 : covers cols 8ql..8ql+7
    int gw = (blockIdx.x * blockDim.x + threadIdx.x) >> 5;
    int nw = (gridDim.x * blockDim.x) >> 5;

    const uint4* P4 = (const uint4*)g_Ph;   // 8 uint4 per node
    const uint4* Q4 = (const uint4*)g_Qh;
    const uint4* ea4 = (const uint4*)g_eah;

    for (int e0 = gw * 4; e0 < E; e0 += nw * 4) {
        int e = e0 + quad;
        if (e < E) {
            int2 rc = __ldg(&g_eidx[e]);
            uint4 up = __ldg(&P4[(size_t)rc.y * 8 + ql]);
            uint4 uq = __ldg(&Q4[(size_t)rc.x * 8 + ql]);
            uint4 ue = __ldg(&ea4[e]);

            float v0, v1, v2, v3, v4, v5, v6, v7;
            {
                float2 p = u_to_f2(up.x), q = u_to_f2(uq.x);
                v0 = p.x + q.x; v1 = p.y + q.y;
                p = u_to_f2(up.y); q = u_to_f2(uq.y);
                v2 = p.x + q.x; v3 = p.y + q.y;
                p = u_to_f2(up.z); q = u_to_f2(uq.z);
                v4 = p.x + q.x; v5 = p.y + q.y;
                p = u_to_f2(up.w); q = u_to_f2(uq.w);
                v6 = p.x + q.x; v7 = p.y + q.y;
            }
#pragma unroll
            for (int jj = 0; jj < 4; jj++) {
                unsigned eu = (jj == 0) ? ue.x : (jj == 1) ? ue.y : (jj == 2) ? ue.z : ue.w;
                float2 ee = u_to_f2(eu);
                int j0 = jj * 2;
                float4 wa = sWc[j0 * 16 + ql * 2];
                float4 wb = sWc[j0 * 16 + ql * 2 + 1];
                v0 = fmaf(ee.x, wa.x, v0); v1 = fmaf(ee.x, wa.y, v1);
                v2 = fmaf(ee.x, wa.z, v2); v3 = fmaf(ee.x, wa.w, v3);
                v4 = fmaf(ee.x, wb.x, v4); v5 = fmaf(ee.x, wb.y, v5);
                v6 = fmaf(ee.x, wb.z, v6); v7 = fmaf(ee.x, wb.w, v7);
                wa = sWc[(j0 + 1) * 16 + ql * 2];
                wb = sWc[(j0 + 1) * 16 + ql * 2 + 1];
                v0 = fmaf(ee.y, wa.x, v0); v1 = fmaf(ee.y, wa.y, v1);
                v2 = fmaf(ee.y, wa.z, v2); v3 = fmaf(ee.y, wa.w, v3);
                v4 = fmaf(ee.y, wb.x, v4); v5 = fmaf(ee.y, wb.y, v5);
                v6 = fmaf(ee.y, wb.z, v6); v7 = fmaf(ee.y, wb.w, v7);
            }

            unsigned m0 = h2_to_u(__floats2half2_rn(silu(v0), silu(v1)));
            unsigned m1 = h2_to_u(__floats2half2_rn(silu(v2), silu(v3)));
            unsigned m2 = h2_to_u(__floats2half2_rn(silu(v4), silu(v5)));
            unsigned m3 = h2_to_u(__floats2half2_rn(silu(v6), silu(v7)));
            __half* dst = g_aggHh + (size_t)rc.y * 64 + ql * 8;
            asm volatile("red.global.add.noftz.v4.f16x2 [%0], {%1, %2, %3, %4};"
                         :: "l"(dst), "r"(m0), "r"(m1), "r"(m2), "r"(m3) : "memory");
        }
    }
}

// ---------------- fused node phase (half2 weights; interleaved staging) --------
__global__ void __launch_bounds__(256, 4)
k_node(const float* __restrict__ w2, const float* __restrict__ b2,
       const float* __restrict__ uw1, const float* __restrict__ ub1,
       const float* __restrict__ uw2, const float* __restrict__ ub2,
       const float* __restrict__ ew1, const float* __restrict__ eb1,
       const float* __restrict__ ew2, const float* __restrict__ eb2,
       const int* __restrict__ batch, float* __restrict__ out,
       int N, int do_readout) {
    extern __shared__ float sm[];
    unsigned* uW2  = (unsigned*)sm;               // 2048 u32 (half2)
    unsigned* uUW1 = uW2 + 2048;                  // 4096
    unsigned* uUW2 = uUW1 + 4096;                 // 2048
    unsigned* uEW1 = uUW2 + 2048;                 // 2048  (ends at 10240 words)
    float2* sb2v  = (float2*)(sm + 10240);        // 32 f2
    float2* sub1v = sb2v + 32;
    float2* sub2v = sub1v + 32;
    float2* seb1v = sub2v + 32;
    float2* sew2v = seb1v + 32;                   // ends at 10560 words
    float* sEb2 = sm + 10560;                     // 16 words pad
    float* sIn  = sm + 10576;                     // 8 warps * 256 (128 float2 pairs)
    float* sHid = sm + 12624;                     // 8 warps * 128 (64 float2 pairs)

    for (int u = threadIdx.x; u < 2048; u += blockDim.x) {
        float2 f = ((const float2*)w2)[u];
        uW2[u] = h2_to_u(__floats2half2_rn(f.x, f.y));
    }
    for (int u = threadIdx.x; u < 4096; u += blockDim.x) {
        float2 f = ((const float2*)uw1)[u];
        uUW1[u] = h2_to_u(__floats2half2_rn(f.x, f.y));
    }
    for (int u = threadIdx.x; u < 2048; u += blockDim.x) {
        float2 f = ((const float2*)uw2)[u];
        uUW2[u] = h2_to_u(__floats2half2_rn(f.x, f.y));
    }
    if (do_readout) {
        for (int u = threadIdx.x; u < 2048; u += blockDim.x) {
            float2 f = ((const float2*)ew1)[u];
            uEW1[u] = h2_to_u(__floats2half2_rn(f.x, f.y));
        }
    }
    if (threadIdx.x < 32) {
        sb2v[threadIdx.x]  = ((const float2*)b2)[threadIdx.x];
        sub1v[threadIdx.x] = ((const float2*)ub1)[threadIdx.x];
        sub2v[threadIdx.x] = ((const float2*)ub2)[threadIdx.x];
        if (do_readout) {
            seb1v[threadIdx.x] = ((const float2*)eb1)[threadIdx.x];
            sew2v[threadIdx.x] = ((const float2*)ew2)[threadIdx.x];
        }
    }
    if (threadIdx.x == 0) sEb2[0] = do_readout ? eb2[0] : 0.0f;
    __syncthreads();

    int warp = threadIdx.x >> 5, lane = threadIdx.x & 31;
    int gw = (blockIdx.x * blockDim.x + threadIdx.x) >> 5;
    int nw = (gridDim.x * blockDim.x) >> 5;
    float2* inP  = (float2*)(sIn + warp * 256);   // 128 pairs
    float2* hidP = (float2*)(sHid + warp * 128);  // 64 pairs

    const float2* X2r = (const float2*)g_x;
    float2* X2w = (float2*)g_x;
    const unsigned* AGH = (const unsigned*)g_aggHh;   // fp16x2 accumulators

    for (int r0 = gw * 2; r0 < N; r0 += nw * 2) {
        int nr = min(2, N - r0);

        // --- phase A: agg = aggH @ W2 + deg*b2 (interleaved pairs) ---
        {
            float2 ag0 = u_to_f2(AGH[(size_t)r0 * 32 + lane]);
            float2 ag1 = (nr > 1) ? u_to_f2(AGH[(size_t)(r0 + 1) * 32 + lane])
                                  : make_float2(0.f, 0.f);
            hidP[2 * lane]     = make_float2(ag0.x, ag1.x);
            hidP[2 * lane + 1] = make_float2(ag0.y, ag1.y);
        }
        __syncwarp();

        float2 agg[2] = {make_float2(0.f, 0.f), make_float2(0.f, 0.f)};
#pragma unroll 8
        for (int k = 0; k < 64; k++) {
            float2 a = hidP[k];                       // (row0[k], row1[k])
            float2 b = u_to_f2(uW2[k * 32 + lane]);
            agg[0].x = fmaf(a.x, b.x, agg[0].x); agg[0].y = fmaf(a.x, b.y, agg[0].y);
            agg[1].x = fmaf(a.y, b.x, agg[1].x); agg[1].y = fmaf(a.y, b.y, agg[1].y);
        }
        float2 bb2 = sb2v[lane];
        float2 xp[2], nx[2];
        nx[0] = nx[1] = make_float2(0.f, 0.f);
#pragma unroll
        for (int rr = 0; rr < 2; rr++) {
            float dg = (rr < nr) ? g_deg[r0 + rr] : 0.0f;
            agg[rr].x = fmaf(dg, bb2.x, agg[rr].x);
            agg[rr].y = fmaf(dg, bb2.y, agg[rr].y);
            if (rr < nr) xp[rr] = X2r[(r0 + rr) * 32 + lane];
            else         xp[rr] = make_float2(0.f, 0.f);
        }
        __syncwarp();

        // --- phase B: stage [x, agg] interleaved ---
        inP[2 * lane]          = make_float2(xp[0].x, xp[1].x);
        inP[2 * lane + 1]      = make_float2(xp[0].y, xp[1].y);
        inP[64 + 2 * lane]     = make_float2(agg[0].x, agg[1].x);
        inP[64 + 2 * lane + 1] = make_float2(agg[0].y, agg[1].y);
        __syncwarp();

        // --- phase C: hidden = silu([x,agg]@uW1 + ub1) ---
        float2 ub1p = sub1v[lane];
        float2 acc[2] = {ub1p, ub1p};
#pragma unroll 8
        for (int k = 0; k < 128; k++) {
            float2 a = inP[k];
            float2 w = u_to_f2(uUW1[k * 32 + lane]);
            acc[0].x = fmaf(a.x, w.x, acc[0].x); acc[0].y = fmaf(a.x, w.y, acc[0].y);
            acc[1].x = fmaf(a.y, w.x, acc[1].x); acc[1].y = fmaf(a.y, w.y, acc[1].y);
        }
        __syncwarp();
        hidP[2 * lane]     = make_float2(silu(acc[0].x), silu(acc[1].x));
        hidP[2 * lane + 1] = make_float2(silu(acc[0].y), silu(acc[1].y));
        __syncwarp();

        // --- phase D: o = hid@uW2 + ub2; x += o ---
        float2 ub2p = sub2v[lane];
        float2 o[2] = {ub2p, ub2p};
#pragma unroll 8
        for (int k = 0; k < 64; k++) {
            float2 a = hidP[k];
            float2 w = u_to_f2(uUW2[k * 32 + lane]);
            o[0].x = fmaf(a.x, w.x, o[0].x); o[0].y = fmaf(a.x, w.y, o[0].y);
            o[1].x = fmaf(a.y, w.x, o[1].x); o[1].y = fmaf(a.y, w.y, o[1].y);
        }
        for (int rr = 0; rr < nr; rr++) {
            nx[rr].x = xp[rr].x + o[rr].x;
            nx[rr].y = xp[rr].y + o[rr].y;
            X2w[(r0 + rr) * 32 + lane] = nx[rr];
        }

        // --- phase E: readout (last layer only) ---
        if (do_readout) {
            __syncwarp();
            inP[2 * lane]     = make_float2(nx[0].x, nx[1].x);
            inP[2 * lane + 1] = make_float2(nx[0].y, nx[1].y);
            __syncwarp();
            float2 eb1p = seb1v[lane];
            float2 ec[2] = {eb1p, eb1p};
#pragma unroll 8
            for (int k = 0; k < 64; k++) {
                float2 a = inP[k];
                float2 w = u_to_f2(uEW1[k * 32 + lane]);
                ec[0].x = fmaf(a.x, w.x, ec[0].x); ec[0].y = fmaf(a.x, w.y, ec[0].y);
                ec[1].x = fmaf(a.y, w.x, ec[1].x); ec[1].y = fmaf(a.y, w.y, ec[1].y);
            }
            float2 w2p = sew2v[lane];
            for (int rr = 0; rr < nr; rr++) {
                float pe = silu(ec[rr].x) * w2p.x + silu(ec[rr].y) * w2p.y;
#pragma unroll
                for (int off = 16; off > 0; off >>= 1)
                    pe += __shfl_xor_sync(0xFFFFFFFF, pe, off);
                if (lane == 0)
                    atomicAdd(&out[batch[r0 + rr]], pe + sEb2[0]);
            }
        }
        __syncwarp();
    }
}

// ------------------------------- host side ------------------------------------
extern "C" void kernel_launch(void* const* d_in, const int* in_sizes, int n_in,
                              void* d_out, int out_size) {
    const int* z = (const int*)d_in[0];
    const float* pos = (const float*)d_in[1];
    const int* ei = (const int*)d_in[2];
    const int* batch = (const int*)d_in[3];
    const float* embed = (const float*)d_in[4];
    const float* msg_w1 = (const float*)d_in[5];
    const float* msg_b1 = (const float*)d_in[6];
    const float* msg_w2 = (const float*)d_in[7];
    const float* msg_b2 = (const float*)d_in[8];
    const float* upd_w1 = (const float*)d_in[9];
    const float* upd_b1 = (const float*)d_in[10];
    const float* upd_w2 = (const float*)d_in[11];
    const float* upd_b2 = (const float*)d_in[12];
    const float* eh_w1 = (const float*)d_in[13];
    const float* eh_b1 = (const float*)d_in[14];
    const float* eh_w2 = (const float*)d_in[15];
    const float* eh_b2 = (const float*)d_in[16];
    float* out = (float*)d_out;

    int N = in_sizes[0];
    int E = in_sizes[2] / 2;

    float* p_deg; cudaGetSymbolAddress((void**)&p_deg, g_deg);

    static bool attr_set = false;
    if (!attr_set) {
        cudaFuncSetAttribute(k_node, cudaFuncAttributeMaxDynamicSharedMemorySize, 13648 * 4);
        attr_set = true;
    }

    const int TPB = 256;
    const int EBLK = 148 * 6;   // one full resident wave for k_edge (6 blocks/SM)
    const int NODB = 148 * 4;   // one full resident wave for k_node (4 blocks/SM)

    // prologue (slot #4 in the capture = k_edge of layer 0)
    k_zero2<<<128, TPB>>>(p_deg, N, out, out_size);
    k_edge_attr<<<1184, TPB>>>(ei, pos, E);

    for (int l = 0; l < NL; l++) {
        const float* w1 = msg_w1 + l * 136 * 64;
        const float* b1 = msg_b1 + l * 64;
        const float* w2 = msg_w2 + l * 64 * 64;
        const float* b2 = msg_b2 + l * 64;
        const float* uw1 = upd_w1 + l * 128 * 64;
        const float* ub1 = upd_b1 + l * 64;
        const float* uw2 = upd_w2 + l * 64 * 64;
        const float* ub2 = upd_b2 + l * 64;

        k_pq<<<740, TPB>>>(w1, b1, (l == 0) ? z : nullptr,
                           (l == 0) ? embed : nullptr, N);
        k_edge<<<EBLK, TPB>>>(w1, E);
        k_node<<<NODB, TPB, 13648 * 4>>>(w2, b2, uw1, ub1, uw2, ub2,
                                         eh_w1, eh_b1, eh_w2, eh_b2,
                                         batch, out, N, (l == NL - 1) ? 1 : 0);
    }
}

// round 14
// speedup vs baseline: 1.2429x; 1.2429x over previous
#include <cuda_runtime.h>
#include <cuda_fp16.h>
#include <math.h>

#define H 64
#define NB 8
#define NL 2
#define MAXN 50000
#define MAXE 800000

// ---------------- scratch (device globals; no allocation allowed) ------------
__device__ __align__(256) float  g_x[MAXN * H];
__device__ __align__(256) __half g_Ph[MAXN * H];    // x@W1a + b1 (fp16)
__device__ __align__(256) __half g_Qh[MAXN * H];    // x@W1b      (fp16)
__device__ __align__(256) __half g_aggHh[MAXN * H]; // fp16 accumulator
__device__ __align__(256) __half g_eah[MAXE * NB];  // edge attrs (fp16)
__device__ __align__(256) int2   g_eidx[MAXE];      // packed (row, col)
__device__ __align__(256) float  g_deg[MAXN];
__device__ __align__(256) float4 g_pos4[MAXN];      // packed positions

__device__ __forceinline__ float silu(float v) {
    return __fdividef(v, 1.0f + __expf(-v));
}

__device__ __forceinline__ unsigned h2_to_u(__half2 h) {
    return *reinterpret_cast<unsigned*>(&h);
}
__device__ __forceinline__ float2 u_to_f2(unsigned u) {
    __half2 h = *reinterpret_cast<__half2*>(&u);
    return __half22float2(h);
}

// ---------------- zero deg + out; pack pos into float4 -------------------------
__global__ void k_prep(const float* __restrict__ pos, int N,
                       float* __restrict__ deg, float* __restrict__ out, int nout) {
    int i = blockIdx.x * blockDim.x + threadIdx.x;
    int stride = gridDim.x * blockDim.x;
    for (int t = i; t < N; t += stride) {
        deg[t] = 0.0f;
        g_pos4[t] = make_float4(pos[t * 3 + 0], pos[t * 3 + 1], pos[t * 3 + 2], 0.0f);
    }
    for (int t = i; t < nout; t += stride) out[t] = 0.0f;
}

// ---------------- edge_attr (fp16) + degree + packed index ---------------------
__global__ void k_edge_attr(const int* __restrict__ ei, int E) {
    int e = blockIdx.x * blockDim.x + threadIdx.x;
    int stride = gridDim.x * blockDim.x;
    const float PI = 3.14159265358979323846f;
    uint4* ea4 = (uint4*)g_eah;
    for (; e < E; e += stride) {
        int r = __ldg(&ei[e]), c = __ldg(&ei[E + e]);
        g_eidx[e] = make_int2(r, c);
        float4 pr = __ldg(&g_pos4[r]);
        float4 pc = __ldg(&g_pos4[c]);
        float dx = pr.x - pc.x;
        float dy = pr.y - pc.y;
        float dz = pr.z - pc.z;
        float d = sqrtf(dx * dx + dy * dy + dz * dz);
        float env = 0.0f;
        if (d < 5.0f) {
            float cv = __cosf(d * (PI / 10.0f));
            env = cv * cv;
        }
        float inv = __fdividef(env, (d > 0.0f) ? d : 1.0f);
        float s1, c1;
        __sincosf(d * (PI / 5.0f), &s1, &c1);
        float twoc = 2.0f * c1;
        float sp = 0.0f, sc = s1;   // sin(k*theta) recurrence
        float v[NB];
#pragma unroll
        for (int j = 0; j < NB; j++) {
            v[j] = sc * inv;
            float sn = twoc * sc - sp;
            sp = sc; sc = sn;
        }
        uint4 u;
        u.x = h2_to_u(__floats2half2_rn(v[0], v[1]));
        u.y = h2_to_u(__floats2half2_rn(v[2], v[3]));
        u.z = h2_to_u(__floats2half2_rn(v[4], v[5]));
        u.w = h2_to_u(__floats2half2_rn(v[6], v[7]));
        ea4[e] = u;
        atomicAdd(&g_deg[c], 1.0f);
    }
}

// ---------------- P = x@W1a + b1, Q = x@W1b (fp16 out); zero aggH; opt gather ---
// lane l<16: P cols 4l..4l+3 ; lane>=16: Q cols 4(l-16)..
__global__ void k_pq(const float* __restrict__ w1, const float* __restrict__ b1,
                     const int* __restrict__ z, const float* __restrict__ embed, int N) {
    __shared__ float4 sB[64 * 32];   // [k][lane]
    __shared__ float4 sb1[16];
    __shared__ float4 sA4[8][64];    // 4 rows x 16 f4 per warp

    const float4* w1v = (const float4*)w1;
    for (int u = threadIdx.x; u < 64 * 32; u += blockDim.x) {
        int k = u >> 5, l = u & 31;
        sB[u] = (l < 16) ? w1v[k * 16 + l] : w1v[(64 + k) * 16 + (l - 16)];
    }
    if (threadIdx.x < 16) sb1[threadIdx.x] = ((const float4*)b1)[threadIdx.x];
    __syncthreads();

    int warp = threadIdx.x >> 5, lane = threadIdx.x & 31;
    int gw = (blockIdx.x * blockDim.x + threadIdx.x) >> 5;
    int nw = (gridDim.x * blockDim.x) >> 5;

    uint2* P2 = (uint2*)g_Ph;    // per node: 16 uint2 (4 halves each)
    uint2* Q2 = (uint2*)g_Qh;
    uint2* Z2 = (uint2*)g_aggHh; // per node: 16 uint2 (fp16 zero fill)
    float4* X4 = (float4*)g_x;
    const float4* E4 = (const float4*)embed;
    float* sA = (float*)sA4[warp];

    bool gather = (z != nullptr);

    for (int r0 = gw * 4; r0 < N; r0 += nw * 4) {
        int nr = min(4, N - r0);
        if (gather) {
            for (int t = lane; t < nr * 16; t += 32) {
                int rr = t >> 4, cc = t & 15;
                float4 v = E4[(size_t)__ldg(&z[r0 + rr]) * 16 + cc];
                sA4[warp][t] = v;
                X4[(size_t)(r0 + rr) * 16 + cc] = v;
            }
        } else {
            for (int t = lane; t < nr * 16; t += 32)
                sA4[warp][t] = X4[(size_t)r0 * 16 + t];
        }
        __syncwarp();

        float4 acc[4];
#pragma unroll
        for (int rr = 0; rr < 4; rr++)
            acc[rr] = (lane < 16) ? sb1[lane & 15] : make_float4(0.f, 0.f, 0.f, 0.f);

#pragma unroll 8
        for (int k = 0; k < 64; k++) {
            float4 b = sB[k * 32 + lane];
#pragma unroll
            for (int rr = 0; rr < 4; rr++) {
                float a = sA[rr * 64 + k];
                acc[rr].x = fmaf(a, b.x, acc[rr].x);
                acc[rr].y = fmaf(a, b.y, acc[rr].y);
                acc[rr].z = fmaf(a, b.z, acc[rr].z);
                acc[rr].w = fmaf(a, b.w, acc[rr].w);
            }
        }
        for (int rr = 0; rr < nr; rr++) {
            size_t b = (size_t)(r0 + rr) * 16;
            uint2 u;
            u.x = h2_to_u(__floats2half2_rn(acc[rr].x, acc[rr].y));
            u.y = h2_to_u(__floats2half2_rn(acc[rr].z, acc[rr].w));
            if (lane < 16) {
                P2[b + lane] = u;
                Z2[b + lane] = make_uint2(0u, 0u);
            } else {
                Q2[b + (lane - 16)] = u;
            }
        }
        __syncwarp();
    }
}

// ---------------- edge phase: aggH[c] += silu(P[c]+Q[r]+ea@W1c) ----------------
// half-warp per edge; lane covers 4 output cols; fp16x2 vector reduction
// (R12 configuration: 32 regs, 8 blocks/SM, one exact wave)
__global__ void __launch_bounds__(256, 8)
k_edge(const float* __restrict__ w1, int E) {
    __shared__ float4 sWc[NB * 16];
    const float4* wc = (const float4*)(w1 + 128 * 64);
    for (int u = threadIdx.x; u < NB * 16; u += blockDim.x) sWc[u] = wc[u];
    __syncthreads();

    int lane = threadIdx.x & 31;
    int half = lane >> 4;
    int hl = lane & 15;
    int gw = (blockIdx.x * blockDim.x + threadIdx.x) >> 5;
    int nw = (gridDim.x * blockDim.x) >> 5;

    const uint2* P2 = (const uint2*)g_Ph;
    const uint2* Q2 = (const uint2*)g_Qh;
    const uint4* ea4 = (const uint4*)g_eah;

    for (int e0 = gw * 2; e0 < E; e0 += nw * 2) {
        int e = e0 + half;
        if (e < E) {
            int2 rc = __ldg(&g_eidx[e]);
            int r = rc.x, c = rc.y;
            uint2 up = __ldg(&P2[(size_t)c * 16 + hl]);
            uint2 uq = __ldg(&Q2[(size_t)r * 16 + hl]);
            uint4 ue = __ldg(&ea4[e]);

            float4 v;
            {
                float2 p = u_to_f2(up.x);
                float2 q = u_to_f2(uq.x);
                v.x = p.x + q.x; v.y = p.y + q.y;
                p = u_to_f2(up.y);
                q = u_to_f2(uq.y);
                v.z = p.x + q.x; v.w = p.y + q.y;
            }
            {
                float2 ee = u_to_f2(ue.x);
                float4 w = sWc[0 * 16 + hl];
                v.x = fmaf(ee.x, w.x, v.x); v.y = fmaf(ee.x, w.y, v.y);
                v.z = fmaf(ee.x, w.z, v.z); v.w = fmaf(ee.x, w.w, v.w);
                w = sWc[1 * 16 + hl];
                v.x = fmaf(ee.y, w.x, v.x); v.y = fmaf(ee.y, w.y, v.y);
                v.z = fmaf(ee.y, w.z, v.z); v.w = fmaf(ee.y, w.w, v.w);
            }
            {
                float2 ee = u_to_f2(ue.y);
                float4 w = sWc[2 * 16 + hl];
                v.x = fmaf(ee.x, w.x, v.x); v.y = fmaf(ee.x, w.y, v.y);
                v.z = fmaf(ee.x, w.z, v.z); v.w = fmaf(ee.x, w.w, v.w);
                w = sWc[3 * 16 + hl];
                v.x = fmaf(ee.y, w.x, v.x); v.y = fmaf(ee.y, w.y, v.y);
                v.z = fmaf(ee.y, w.z, v.z); v.w = fmaf(ee.y, w.w, v.w);
            }
            {
                float2 ee = u_to_f2(ue.z);
                float4 w = sWc[4 * 16 + hl];
                v.x = fmaf(ee.x, w.x, v.x); v.y = fmaf(ee.x, w.y, v.y);
                v.z = fmaf(ee.x, w.z, v.z); v.w = fmaf(ee.x, w.w, v.w);
                w = sWc[5 * 16 + hl];
                v.x = fmaf(ee.y, w.x, v.x); v.y = fmaf(ee.y, w.y, v.y);
                v.z = fmaf(ee.y, w.z, v.z); v.w = fmaf(ee.y, w.w, v.w);
            }
            {
                float2 ee = u_to_f2(ue.w);
                float4 w = sWc[6 * 16 + hl];
                v.x = fmaf(ee.x, w.x, v.x); v.y = fmaf(ee.x, w.y, v.y);
                v.z = fmaf(ee.x, w.z, v.z); v.w = fmaf(ee.x, w.w, v.w);
                w = sWc[7 * 16 + hl];
                v.x = fmaf(ee.y, w.x, v.x); v.y = fmaf(ee.y, w.y, v.y);
                v.z = fmaf(ee.y, w.z, v.z); v.w = fmaf(ee.y, w.w, v.w);
            }

            unsigned m01 = h2_to_u(__floats2half2_rn(silu(v.x), silu(v.y)));
            unsigned m23 = h2_to_u(__floats2half2_rn(silu(v.z), silu(v.w)));
            __half* dst = g_aggHh + (size_t)c * 64 + hl * 4;
            asm volatile("red.global.add.noftz.v2.f16x2 [%0], {%1, %2};"
                         :: "l"(dst), "r"(m01), "r"(m23) : "memory");
        }
    }
}

// ---------------- fused node phase (half2 weights; interleaved staging) --------
__global__ void __launch_bounds__(256, 4)
k_node(const float* __restrict__ w2, const float* __restrict__ b2,
       const float* __restrict__ uw1, const float* __restrict__ ub1,
       const float* __restrict__ uw2, const float* __restrict__ ub2,
       const float* __restrict__ ew1, const float* __restrict__ eb1,
       const float* __restrict__ ew2, const float* __restrict__ eb2,
       const int* __restrict__ batch, float* __restrict__ out,
       int N, int do_readout) {
    extern __shared__ float sm[];
    unsigned* uW2  = (unsigned*)sm;               // 2048 u32 (half2)
    unsigned* uUW1 = uW2 + 2048;                  // 4096
    unsigned* uUW2 = uUW1 + 4096;                 // 2048
    unsigned* uEW1 = uUW2 + 2048;                 // 2048  (ends at 10240 words)
    float2* sb2v  = (float2*)(sm + 10240);        // 32 f2
    float2* sub1v = sb2v + 32;
    float2* sub2v = sub1v + 32;
    float2* seb1v = sub2v + 32;
    float2* sew2v = seb1v + 32;                   // ends at 10560 words
    float* sEb2 = sm + 10560;                     // 16 words pad
    float* sIn  = sm + 10576;                     // 8 warps * 256 (128 float2 pairs)
    float* sHid = sm + 12624;                     // 8 warps * 128 (64 float2 pairs)

    for (int u = threadIdx.x; u < 2048; u += blockDim.x) {
        float2 f = ((const float2*)w2)[u];
        uW2[u] = h2_to_u(__floats2half2_rn(f.x, f.y));
    }
    for (int u = threadIdx.x; u < 4096; u += blockDim.x) {
        float2 f = ((const float2*)uw1)[u];
        uUW1[u] = h2_to_u(__floats2half2_rn(f.x, f.y));
    }
    for (int u = threadIdx.x; u < 2048; u += blockDim.x) {
        float2 f = ((const float2*)uw2)[u];
        uUW2[u] = h2_to_u(__floats2half2_rn(f.x, f.y));
    }
    if (do_readout) {
        for (int u = threadIdx.x; u < 2048; u += blockDim.x) {
            float2 f = ((const float2*)ew1)[u];
            uEW1[u] = h2_to_u(__floats2half2_rn(f.x, f.y));
        }
    }
    if (threadIdx.x < 32) {
        sb2v[threadIdx.x]  = ((const float2*)b2)[threadIdx.x];
        sub1v[threadIdx.x] = ((const float2*)ub1)[threadIdx.x];
        sub2v[threadIdx.x] = ((const float2*)ub2)[threadIdx.x];
        if (do_readout) {
            seb1v[threadIdx.x] = ((const float2*)eb1)[threadIdx.x];
            sew2v[threadIdx.x] = ((const float2*)ew2)[threadIdx.x];
        }
    }
    if (threadIdx.x == 0) sEb2[0] = do_readout ? eb2[0] : 0.0f;
    __syncthreads();

    int warp = threadIdx.x >> 5, lane = threadIdx.x & 31;
    int gw = (blockIdx.x * blockDim.x + threadIdx.x) >> 5;
    int nw = (gridDim.x * blockDim.x) >> 5;
    float2* inP  = (float2*)(sIn + warp * 256);   // 128 pairs
    float2* hidP = (float2*)(sHid + warp * 128);  // 64 pairs

    const float2* X2r = (const float2*)g_x;
    float2* X2w = (float2*)g_x;
    const unsigned* AGH = (const unsigned*)g_aggHh;   // fp16x2 accumulators

    for (int r0 = gw * 2; r0 < N; r0 += nw * 2) {
        int nr = min(2, N - r0);

        // --- phase A: agg = aggH @ W2 + deg*b2 (interleaved pairs) ---
        {
            float2 ag0 = u_to_f2(AGH[(size_t)r0 * 32 + lane]);
            float2 ag1 = (nr > 1) ? u_to_f2(AGH[(size_t)(r0 + 1) * 32 + lane])
                                  : make_float2(0.f, 0.f);
            hidP[2 * lane]     = make_float2(ag0.x, ag1.x);
            hidP[2 * lane + 1] = make_float2(ag0.y, ag1.y);
        }
        __syncwarp();

        float2 agg[2] = {make_float2(0.f, 0.f), make_float2(0.f, 0.f)};
#pragma unroll 8
        for (int k = 0; k < 64; k++) {
            float2 a = hidP[k];                       // (row0[k], row1[k])
            float2 b = u_to_f2(uW2[k * 32 + lane]);
            agg[0].x = fmaf(a.x, b.x, agg[0].x); agg[0].y = fmaf(a.x, b.y, agg[0].y);
            agg[1].x = fmaf(a.y, b.x, agg[1].x); agg[1].y = fmaf(a.y, b.y, agg[1].y);
        }
        float2 bb2 = sb2v[lane];
        float2 xp[2], nx[2];
        nx[0] = nx[1] = make_float2(0.f, 0.f);
#pragma unroll
        for (int rr = 0; rr < 2; rr++) {
            float dg = (rr < nr) ? g_deg[r0 + rr] : 0.0f;
            agg[rr].x = fmaf(dg, bb2.x, agg[rr].x);
            agg[rr].y = fmaf(dg, bb2.y, agg[rr].y);
            if (rr < nr) xp[rr] = X2r[(r0 + rr) * 32 + lane];
            else         xp[rr] = make_float2(0.f, 0.f);
        }
        __syncwarp();

        // --- phase B: stage [x, agg] interleaved ---
        inP[2 * lane]          = make_float2(xp[0].x, xp[1].x);
        inP[2 * lane + 1]      = make_float2(xp[0].y, xp[1].y);
        inP[64 + 2 * lane]     = make_float2(agg[0].x, agg[1].x);
        inP[64 + 2 * lane + 1] = make_float2(agg[0].y, agg[1].y);
        __syncwarp();

        // --- phase C: hidden = silu([x,agg]@uW1 + ub1) ---
        float2 ub1p = sub1v[lane];
        float2 acc[2] = {ub1p, ub1p};
#pragma unroll 8
        for (int k = 0; k < 128; k++) {
            float2 a = inP[k];
            float2 w = u_to_f2(uUW1[k * 32 + lane]);
            acc[0].x = fmaf(a.x, w.x, acc[0].x); acc[0].y = fmaf(a.x, w.y, acc[0].y);
            acc[1].x = fmaf(a.y, w.x, acc[1].x); acc[1].y = fmaf(a.y, w.y, acc[1].y);
        }
        __syncwarp();
        hidP[2 * lane]     = make_float2(silu(acc[0].x), silu(acc[1].x));
        hidP[2 * lane + 1] = make_float2(silu(acc[0].y), silu(acc[1].y));
        __syncwarp();

        // --- phase D: o = hid@uW2 + ub2; x += o ---
        float2 ub2p = sub2v[lane];
        float2 o[2] = {ub2p, ub2p};
#pragma unroll 8
        for (int k = 0; k < 64; k++) {
            float2 a = hidP[k];
            float2 w = u_to_f2(uUW2[k * 32 + lane]);
            o[0].x = fmaf(a.x, w.x, o[0].x); o[0].y = fmaf(a.x, w.y, o[0].y);
            o[1].x = fmaf(a.y, w.x, o[1].x); o[1].y = fmaf(a.y, w.y, o[1].y);
        }
        for (int rr = 0; rr < nr; rr++) {
            nx[rr].x = xp[rr].x + o[rr].x;
            nx[rr].y = xp[rr].y + o[rr].y;
            X2w[(r0 + rr) * 32 + lane] = nx[rr];
        }

        // --- phase E: readout (last layer only) ---
        if (do_readout) {
            __syncwarp();
            inP[2 * lane]     = make_float2(nx[0].x, nx[1].x);
            inP[2 * lane + 1] = make_float2(nx[0].y, nx[1].y);
            __syncwarp();
            float2 eb1p = seb1v[lane];
            float2 ec[2] = {eb1p, eb1p};
#pragma unroll 8
            for (int k = 0; k < 64; k++) {
                float2 a = inP[k];
                float2 w = u_to_f2(uEW1[k * 32 + lane]);
                ec[0].x = fmaf(a.x, w.x, ec[0].x); ec[0].y = fmaf(a.x, w.y, ec[0].y);
                ec[1].x = fmaf(a.y, w.x, ec[1].x); ec[1].y = fmaf(a.y, w.y, ec[1].y);
            }
            float2 w2p = sew2v[lane];
            for (int rr = 0; rr < nr; rr++) {
                float pe = silu(ec[rr].x) * w2p.x + silu(ec[rr].y) * w2p.y;
#pragma unroll
                for (int off = 16; off > 0; off >>= 1)
                    pe += __shfl_xor_sync(0xFFFFFFFF, pe, off);
                if (lane == 0)
                    atomicAdd(&out[batch[r0 + rr]], pe + sEb2[0]);
            }
        }
        __syncwarp();
    }
}

// ------------------------------- host side ------------------------------------
extern "C" void kernel_launch(void* const* d_in, const int* in_sizes, int n_in,
                              void* d_out, int out_size) {
    const int* z = (const int*)d_in[0];
    const float* pos = (const float*)d_in[1];
    const int* ei = (const int*)d_in[2];
    const int* batch = (const int*)d_in[3];
    const float* embed = (const float*)d_in[4];
    const float* msg_w1 = (const float*)d_in[5];
    const float* msg_b1 = (const float*)d_in[6];
    const float* msg_w2 = (const float*)d_in[7];
    const float* msg_b2 = (const float*)d_in[8];
    const float* upd_w1 = (const float*)d_in[9];
    const float* upd_b1 = (const float*)d_in[10];
    const float* upd_w2 = (const float*)d_in[11];
    const float* upd_b2 = (const float*)d_in[12];
    const float* eh_w1 = (const float*)d_in[13];
    const float* eh_b1 = (const float*)d_in[14];
    const float* eh_w2 = (const float*)d_in[15];
    const float* eh_b2 = (const float*)d_in[16];
    float* out = (float*)d_out;

    int N = in_sizes[0];
    int E = in_sizes[2] / 2;

    float* p_deg; cudaGetSymbolAddress((void**)&p_deg, g_deg);

    static bool attr_set = false;
    if (!attr_set) {
        cudaFuncSetAttribute(k_node, cudaFuncAttributeMaxDynamicSharedMemorySize, 13648 * 4);
        attr_set = true;
    }

    const int TPB = 256;
    const int EBLK = 148 * 8;   // one full resident wave for k_edge (8 blocks/SM)
    const int NODB = 148 * 4;   // one full resident wave for k_node (4 blocks/SM)

    // prologue
    k_prep<<<256, TPB>>>(pos, N, p_deg, out, out_size);
    k_edge_attr<<<1184, TPB>>>(ei, E);

    for (int l = 0; l < NL; l++) {
        const float* w1 = msg_w1 + l * 136 * 64;
        const float* b1 = msg_b1 + l * 64;
        const float* w2 = msg_w2 + l * 64 * 64;
        const float* b2 = msg_b2 + l * 64;
        const float* uw1 = upd_w1 + l * 128 * 64;
        const float* ub1 = upd_b1 + l * 64;
        const float* uw2 = upd_w2 + l * 64 * 64;
        const float* ub2 = upd_b2 + l * 64;

        k_pq<<<740, TPB>>>(w1, b1, (l == 0) ? z : nullptr,
                           (l == 0) ? embed : nullptr, N);
        k_edge<<<EBLK, TPB>>>(w1, E);
        k_node<<<NODB, TPB, 13648 * 4>>>(w2, b2, uw1, ub1, uw2, ub2,
                                         eh_w1, eh_b1, eh_w2, eh_b2,
                                         batch, out, N, (l == NL - 1) ? 1 : 0);
    }
}